// round 11
// baseline (speedup 1.0000x reference)
#include <cuda_runtime.h>
#include <cuda_fp16.h>
#include <cstdint>

#define HH 128
#define WW 128
#define BB 16
#define HW (HH * WW)

// ---------------- scratch (static device globals; no runtime alloc) --------
__device__ __half g_inh[(size_t)BB * HW * 64];     // input, NHWC fp16
__device__ __half g_c1h[(size_t)BB * HW * 256];    // conv1 out, NHWC fp16
__device__ __half g_c2h[(size_t)BB * HW * 128];    // conv2 out, NHWC fp16
__device__ __half g_edgeh[(size_t)BB * HW * 128];  // sobel out, NHWC fp16
__device__ __half g_w1h[256 * 64];
__device__ __half g_w2h[128 * 2304];
__device__ __half g_w3h[64 * 1152];
__device__ float g_b1f[256];
__device__ float g_b2f[128];
__device__ float g_b3f[64];

// ---------------- helpers ---------------------------------------------------
__device__ __forceinline__ uint32_t smem_u32(const void* p) {
    uint32_t a;
    asm("{ .reg .u64 t; cvta.to.shared.u64 t, %1; cvt.u32.u64 %0, t; }" : "=r"(a) : "l"(p));
    return a;
}
__device__ __forceinline__ void cp_async16(uint32_t dst, const void* src, int srcBytes) {
    asm volatile("cp.async.cg.shared.global [%0], [%1], 16, %2;\n"
                 :: "r"(dst), "l"(src), "r"(srcBytes) : "memory");
}
#define CP_COMMIT() asm volatile("cp.async.commit_group;" ::: "memory")
#define CP_WAIT(n)  asm volatile("cp.async.wait_group %0;" :: "n"(n) : "memory")

__device__ __forceinline__ void ldsm_x4(uint32_t* r, uint32_t addr) {
    asm volatile("ldmatrix.sync.aligned.m8n8.x4.shared.b16 {%0,%1,%2,%3}, [%4];"
                 : "=r"(r[0]), "=r"(r[1]), "=r"(r[2]), "=r"(r[3]) : "r"(addr));
}
__device__ __forceinline__ void mma16816(float* c, const uint32_t* a, uint32_t b0, uint32_t b1) {
    asm volatile(
        "mma.sync.aligned.m16n8k16.row.col.f32.f16.f16.f32 "
        "{%0,%1,%2,%3}, {%4,%5,%6,%7}, {%8,%9}, {%0,%1,%2,%3};"
        : "+f"(c[0]), "+f"(c[1]), "+f"(c[2]), "+f"(c[3])
        : "r"(a[0]), "r"(a[1]), "r"(a[2]), "r"(a[3]), "r"(b0), "r"(b1));
}

// ---------------- fp16 HMMA implicit-GEMM conv + bias + ReLU ----------------
// GEMM: M = Co (128/block), N = 128 pixels (one (b,h) image row), K = Ci*KSZ*KSZ.
// BK=32 (2 k16 steps). 128 threads = 4 warps, warp tile 64x64.
// Activations NHWC fp16 -> B rows contiguous. cp.async double-buffered.
// OUTMODE: 0 = NHWC fp16, 2 = NCHW f32 into d_out channels [64,128)
template <int CI, int KSZ, int CO_VALID, int OUTMODE>
__global__ __launch_bounds__(128) void conv_hmma(
    const __half* __restrict__ xh, const __half* __restrict__ wh,
    const float* __restrict__ bfv, void* __restrict__ outp, int Ct) {
    constexpr int K = CI * KSZ * KSZ;
    constexpr int NS = K / 32;
    constexpr int SPP = CI / 32;   // stages per (kh,kw) plane
    constexpr int LDT = 40;        // halfs per smem tile row (padded; ldmatrix conflict-free)
    constexpr int TILE = 128 * LDT;

    __shared__ __align__(16) __half sm[4 * TILE];  // [buf0 A][buf0 B][buf1 A][buf1 B]
    __shared__ float sbias[128];

    const int tid = threadIdx.x;
    const int lane = tid & 31;
    const int wid = tid >> 5;
    const int bh = blockIdx.x;
    const int b = bh >> 7, h = bh & 127;
    const int co0 = blockIdx.y * 128;
    const int m0 = (wid & 1) * 64;
    const int n0 = (wid >> 1) * 64;

    if (tid < 128) sbias[tid] = (co0 + tid < CO_VALID) ? bfv[co0 + tid] : 0.f;

    // per-stage loader: thread t loads row t of A tile and row t of B tile (4 x 16B each)
    auto load_stage = [&](int s, int buf) {
        {   // A (weights): row = co
            bool ok = (co0 + tid) < CO_VALID;
            const __half* src = ok ? (wh + (size_t)(co0 + tid) * K + s * 32) : wh;
            uint32_t d = smem_u32(&sm[(buf * 2 + 0) * TILE + tid * LDT]);
            int sz = ok ? 16 : 0;
#pragma unroll
            for (int seg = 0; seg < 4; seg++) cp_async16(d + seg * 16, src + seg * 8, sz);
        }
        {   // B (im2col NHWC): row = pixel w
            const int khkw = s / SPP;
            const int ci0 = (s - khkw * SPP) * 32;
            const int kh = (KSZ == 3) ? khkw / 3 : 0;
            const int kw = (KSZ == 3) ? khkw % 3 : 0;
            const int ih = h + kh - (KSZ == 3 ? 1 : 0);
            const int iw = tid + kw - (KSZ == 3 ? 1 : 0);
            bool ok = (KSZ == 1) || ((unsigned)ih < 128u && (unsigned)iw < 128u);
            const __half* src = ok ? (xh + (((size_t)b * 128 + ih) * 128 + iw) * CI + ci0) : xh;
            uint32_t d = smem_u32(&sm[(buf * 2 + 1) * TILE + tid * LDT]);
            int sz = ok ? 16 : 0;
#pragma unroll
            for (int seg = 0; seg < 4; seg++) cp_async16(d + seg * 16, src + seg * 8, sz);
        }
    };

    float acc[4][8][4];
#pragma unroll
    for (int i = 0; i < 4; i++)
#pragma unroll
        for (int j = 0; j < 8; j++)
#pragma unroll
            for (int r = 0; r < 4; r++) acc[i][j][r] = 0.f;

    load_stage(0, 0);
    CP_COMMIT();

    for (int s = 0; s < NS; s++) {
        const int buf = s & 1;
        if (s + 1 < NS) {
            load_stage(s + 1, buf ^ 1);
            CP_COMMIT();
            CP_WAIT(1);
        } else {
            CP_WAIT(0);
        }
        __syncthreads();

        const uint32_t Ab = smem_u32(&sm[(buf * 2 + 0) * TILE]);
        const uint32_t Bb = smem_u32(&sm[(buf * 2 + 1) * TILE]);
#pragma unroll
        for (int ks = 0; ks < 2; ks++) {
            const int kb = ks * 16;
            uint32_t af[4][4];
#pragma unroll
            for (int mt = 0; mt < 4; mt++) {
                uint32_t addr = Ab + ((m0 + mt * 16 + (lane & 15)) * LDT + kb + (lane >> 4) * 8) * 2;
                ldsm_x4(af[mt], addr);
            }
            uint32_t bfr[4][4];
#pragma unroll
            for (int p = 0; p < 4; p++) {
                uint32_t addr = Bb + ((n0 + p * 16 + (lane & 7) + ((lane >> 4) << 3)) * LDT
                                      + kb + (lane & 8)) * 2;
                ldsm_x4(bfr[p], addr);
            }
#pragma unroll
            for (int mt = 0; mt < 4; mt++)
#pragma unroll
                for (int nt = 0; nt < 8; nt++)
                    mma16816(acc[mt][nt], af[mt], bfr[nt >> 1][(nt & 1) * 2],
                             bfr[nt >> 1][(nt & 1) * 2 + 1]);
        }
        __syncthreads();
    }

    // ---- epilogue: 4 chunks of 32 pixels via f32 smem [128][34] ----
    float* epi = reinterpret_cast<float*>(sm);
    const int gid = lane >> 2, tig = lane & 3;
    for (int nc = 0; nc < 4; nc++) {
        __syncthreads();
        if ((wid >> 1) == (nc >> 1)) {
#pragma unroll
            for (int mt = 0; mt < 4; mt++) {
#pragma unroll
                for (int j = 0; j < 4; j++) {
                    const int nt = (nc & 1) * 4 + j;
                    const int nl = n0 + nt * 8 + tig * 2 - nc * 32;
                    const int m = m0 + mt * 16 + gid;
                    epi[m * 34 + nl]     = fmaxf(acc[mt][nt][0] + sbias[m], 0.f);
                    epi[m * 34 + nl + 1] = fmaxf(acc[mt][nt][1] + sbias[m], 0.f);
                    const int m2 = m + 8;
                    epi[m2 * 34 + nl]     = fmaxf(acc[mt][nt][2] + sbias[m2], 0.f);
                    epi[m2 * 34 + nl + 1] = fmaxf(acc[mt][nt][3] + sbias[m2], 0.f);
                }
            }
        }
        __syncthreads();
        if (OUTMODE == 0) {
            // NHWC fp16: thread: pixel nl = tid>>2, co segment (tid&3)*32
            const int nl = tid >> 2, cop = (tid & 3) * 32;
            const size_t pix = ((size_t)b * 128 + h) * 128 + nc * 32 + nl;
            __half* op = (__half*)outp + pix * Ct + co0 + cop;
#pragma unroll
            for (int g4 = 0; g4 < 4; g4++) {
                __half hv[8];
#pragma unroll
                for (int i = 0; i < 8; i++)
                    hv[i] = __float2half(epi[(cop + g4 * 8 + i) * 34 + nl]);
                *reinterpret_cast<uint4*>(op + g4 * 8) = *reinterpret_cast<const uint4*>(hv);
            }
        } else {
            // NCHW f32 into d_out channels [64,128): thread: co = tid>>1, 16 pixels
            const int co = tid >> 1, hw16 = (tid & 1) * 16;
            float* op = (float*)outp + ((size_t)b * 128 + 64 + co) * HW + (size_t)h * 128
                        + nc * 32 + hw16;
#pragma unroll
            for (int i = 0; i < 4; i++) {
                float4 v;
                v.x = epi[co * 34 + hw16 + i * 4 + 0];
                v.y = epi[co * 34 + hw16 + i * 4 + 1];
                v.z = epi[co * 34 + hw16 + i * 4 + 2];
                v.w = epi[co * 34 + hw16 + i * 4 + 3];
                *reinterpret_cast<float4*>(op + i * 4) = v;
            }
        }
    }
}

// ---------------- prep kernels ----------------------------------------------
// fold BN into weights, reorder k -> (kh*3+kw)*Ci+ci, convert fp16
__global__ void fuse_bn_pack_kernel(const float* __restrict__ w, const float* __restrict__ b,
                                    const float* __restrict__ g, const float* __restrict__ be,
                                    const float* __restrict__ m, const float* __restrict__ v,
                                    __half* __restrict__ wh, float* __restrict__ bfv,
                                    int Co, int Ci, int KK) {
    int idx = blockIdx.x * blockDim.x + threadIdx.x;
    int K = Ci * KK;
    if (idx < Co * K) {
        int co = idx / K;
        int k = idx - co * K;
        int khkw = k / Ci;
        int ci = k - khkw * Ci;
        float s = g[co] * rsqrtf(v[co] + 1e-5f);
        wh[idx] = __float2half(w[(size_t)(co * Ci + ci) * KK + khkw] * s);
    }
    if (idx < Co) {
        float s = g[idx] * rsqrtf(v[idx] + 1e-5f);
        bfv[idx] = (b[idx] - m[idx]) * s + be[idx];
    }
}

// input NCHW f32 -> NHWC fp16 (per (b,h) row, smem transpose)
__global__ __launch_bounds__(256) void pack_in_kernel(const float* __restrict__ in,
                                                      __half* __restrict__ out) {
    __shared__ float t[64][129];
    const int bh = blockIdx.x;
    const int b = bh >> 7, h = bh & 127;
    const int tid = threadIdx.x;
    {
        const int w = tid & 127, chalf = tid >> 7;
#pragma unroll
        for (int k = 0; k < 32; k++) {
            int c = chalf * 32 + k;
            t[c][w] = in[(((size_t)b * 64 + c) * HH + h) * WW + w];
        }
    }
    __syncthreads();
    {
        const int cp = tid & 31, wseg = tid >> 5;
        __half2* o = reinterpret_cast<__half2*>(out);
#pragma unroll
        for (int j = 0; j < 16; j++) {
            int w = wseg * 16 + j;
            o[(((size_t)b * 128 + h) * 128 + w) * 32 + cp] =
                __floats2half2_rn(t[cp * 2][w], t[cp * 2 + 1][w]);
        }
    }
}

// sobel depthwise on NHWC fp16 (fp32 math), 2 channels per thread
__global__ void sobel_h_kernel(const __half* __restrict__ in, __half* __restrict__ out) {
    int idx = blockIdx.x * blockDim.x + threadIdx.x;
    if (idx >= BB * HW * 64) return;  // half2 units, Ct=128
    const int cp = idx & 63;
    const int w = (idx >> 6) & 127;
    const int h = (idx >> 13) & 127;
    const int b = idx >> 20;
    const __half2* base = reinterpret_cast<const __half2*>(in);
    float sx = 0.f, sy = 0.f;
    const float kern[3][3] = {{2.f, 4.f, 4.f}, {-2.f, 0.f, 2.f}, {-4.f, -4.f, -2.f}};
#pragma unroll
    for (int kh = 0; kh < 3; kh++) {
        int ih = h + kh - 1;
        if ((unsigned)ih >= 128u) continue;
#pragma unroll
        for (int kw = 0; kw < 3; kw++) {
            if (kh == 1 && kw == 1) continue;
            int iw = w + kw - 1;
            if ((unsigned)iw >= 128u) continue;
            float2 v = __half22float2(base[(((size_t)b * 128 + ih) * 128 + iw) * 64 + cp]);
            sx += kern[kh][kw] * v.x;
            sy += kern[kh][kw] * v.y;
        }
    }
    reinterpret_cast<__half2*>(out)[idx] = __floats2half2_rn(sx, sy);
}

// passthrough: input -> d_out channels [0,64)
__global__ void copy_in_kernel(const float* __restrict__ in, float* __restrict__ out) {
    int idx = blockIdx.x * blockDim.x + threadIdx.x;
    const int total = BB * 64 * HW / 4;
    if (idx >= total) return;
    float4 v = reinterpret_cast<const float4*>(in)[idx];
    int fidx = idx * 4;
    int b = fidx / (64 * HW);
    int r = fidx - b * (64 * HW);
    *reinterpret_cast<float4*>(out + (size_t)b * (128 * HW) + r) = v;
}

extern "C" void kernel_launch(void* const* d_in, const int* in_sizes, int n_in,
                              void* d_out, int out_size) {
    const float* input = (const float*)d_in[0];
    const float* w1 = (const float*)d_in[1];
    const float* b1 = (const float*)d_in[2];
    const float* g1 = (const float*)d_in[3];
    const float* be1 = (const float*)d_in[4];
    const float* m1 = (const float*)d_in[5];
    const float* v1 = (const float*)d_in[6];
    const float* w2 = (const float*)d_in[7];
    const float* b2 = (const float*)d_in[8];
    const float* g2 = (const float*)d_in[9];
    const float* be2 = (const float*)d_in[10];
    const float* m2 = (const float*)d_in[11];
    const float* v2 = (const float*)d_in[12];
    const float* w3 = (const float*)d_in[13];
    const float* b3 = (const float*)d_in[14];
    const float* g3 = (const float*)d_in[15];
    const float* be3 = (const float*)d_in[16];
    const float* m3 = (const float*)d_in[17];
    const float* v3 = (const float*)d_in[18];
    float* out = (float*)d_out;

    __half *inh, *c1h, *c2h, *edgeh, *w1h, *w2h, *w3h;
    float *b1f, *b2f, *b3f;
    cudaGetSymbolAddress((void**)&inh, g_inh);
    cudaGetSymbolAddress((void**)&c1h, g_c1h);
    cudaGetSymbolAddress((void**)&c2h, g_c2h);
    cudaGetSymbolAddress((void**)&edgeh, g_edgeh);
    cudaGetSymbolAddress((void**)&w1h, g_w1h);
    cudaGetSymbolAddress((void**)&w2h, g_w2h);
    cudaGetSymbolAddress((void**)&w3h, g_w3h);
    cudaGetSymbolAddress((void**)&b1f, g_b1f);
    cudaGetSymbolAddress((void**)&b2f, g_b2f);
    cudaGetSymbolAddress((void**)&b3f, g_b3f);

    // ---- prep: BN-fold + reorder + fp16 weights; pack input NHWC fp16 ----
    fuse_bn_pack_kernel<<<(256 * 64 + 255) / 256, 256>>>(w1, b1, g1, be1, m1, v1, w1h, b1f, 256, 64, 1);
    fuse_bn_pack_kernel<<<(128 * 2304 + 255) / 256, 256>>>(w2, b2, g2, be2, m2, v2, w2h, b2f, 128, 256, 9);
    fuse_bn_pack_kernel<<<(64 * 1152 + 255) / 256, 256>>>(w3, b3, g3, be3, m3, v3, w3h, b3f, 64, 128, 9);
    pack_in_kernel<<<BB * HH, 256>>>(input, inh);

    // ---- passthrough channels 0..63 ----
    copy_in_kernel<<<(BB * 64 * HW / 4 + 255) / 256, 256>>>(input, out);

    const int NT = BB * HH;  // 2048 (b,h) row tiles

    // conv1: 1x1, 64->256, NHWC fp16 out
    conv_hmma<64, 1, 256, 0><<<dim3(NT, 2), 128>>>(inh, w1h, b1f, c1h, 256);
    // conv2: 3x3, 256->128, NHWC fp16 out
    conv_hmma<256, 3, 128, 0><<<dim3(NT, 1), 128>>>(c1h, w2h, b2f, c2h, 128);
    // sobel depthwise (fp32 math on fp16 data)
    sobel_h_kernel<<<(BB * HW * 64 + 255) / 256, 256>>>(c2h, edgeh);
    // conv3: 3x3, 128->64, NCHW f32 into d_out channels [64,128)
    conv_hmma<128, 3, 64, 2><<<dim3(NT, 1), 128>>>(edgeh, w3h, b3f, out, 0);
}